// round 3
// baseline (speedup 1.0000x reference)
#include <cuda_runtime.h>
#include <math.h>

// Problem caps (N=100000, E=800000 per setup_inputs; small safety margin)
#define NCAP 100352
#define ECAP 802816
#define ETCAP (ECAP + NCAP)

// ---------------- device scratch (static, no allocation) ----------------
__device__ float g_h  [(size_t)NCAP * 128];   // per-layer transformed features
__device__ float g_x1 [(size_t)NCAP * 128];   // layer-1 output
__device__ float g_x2 [(size_t)NCAP * 128];   // layer-2 output
__device__ float g_agg[(size_t)NCAP * 512];   // layer-3 weighted x2 aggregate
__device__ float g_ss [NCAP * 4];             // s_src per node/head
__device__ float g_sd [NCAP * 4];             // s_dst per node/head
__device__ int   g_cnt [NCAP];
__device__ int   g_scan[NCAP];
__device__ int   g_bsum[1024];
__device__ int   g_off [NCAP + 1];
__device__ int   g_cur [NCAP];
__device__ int   g_csrc[ETCAP];
__device__ float g_ws[128 * 4];               // W3_h @ a_src3_h
__device__ float g_wd[128 * 4];               // W3_h @ a_dst3_h
__device__ int   g_i64;                       // 1 if edge_index is int64, 0 if int32

__device__ __forceinline__ float lrelu(float e) { return e > 0.f ? e : 0.2f * e; }

__device__ __forceinline__ int edge_at(const void* ei, int idx) {
    if (g_i64) return (int)((const long long*)ei)[idx];
    return ((const int*)ei)[idx];
}

// ---------------- edge dtype detection ----------------
// If int64 (values < N < 2^31, nonneg), every odd 32-bit word is 0.
// If int32, odd words are random node ids; 4096 all-zero samples ~ impossible.
__global__ void k_detect(const int* __restrict__ ei32, int nsamp) {
    __shared__ int any;
    if (threadIdx.x == 0) any = 0;
    __syncthreads();
    for (int i = threadIdx.x * 2 + 1; i < nsamp; i += 512)
        if (ei32[i] != 0) { any = 1; break; }
    __syncthreads();
    if (threadIdx.x == 0) g_i64 = any ? 0 : 1;
}

// ---------------- CSR build ----------------
__global__ void k_init_cnt(int N) {
    int i = blockIdx.x * blockDim.x + threadIdx.x;
    if (i < N) g_cnt[i] = 1;   // self loop
}

__global__ void k_hist(const void* __restrict__ ei, int E, int N) {
    int e = blockIdx.x * blockDim.x + threadIdx.x;
    if (e >= E) return;
    int dst = edge_at(ei, E + e);
    if ((unsigned)dst < (unsigned)N) atomicAdd(&g_cnt[dst], 1);
}

__global__ void k_scan1(int N) {  // block-wise inclusive scan, 1024/block
    __shared__ int sm[1024];
    int tid = threadIdx.x;
    int i = blockIdx.x * 1024 + tid;
    sm[tid] = (i < N) ? g_cnt[i] : 0;
    __syncthreads();
    for (int off = 1; off < 1024; off <<= 1) {
        int t = (tid >= off) ? sm[tid - off] : 0;
        __syncthreads();
        sm[tid] += t;
        __syncthreads();
    }
    if (i < N) g_scan[i] = sm[tid];
    if (tid == 1023) g_bsum[blockIdx.x] = sm[1023];
}

__global__ void k_scan2(int nb) {  // scan block sums (single block)
    __shared__ int sm[1024];
    int tid = threadIdx.x;
    sm[tid] = (tid < nb) ? g_bsum[tid] : 0;
    __syncthreads();
    for (int off = 1; off < 1024; off <<= 1) {
        int t = (tid >= off) ? sm[tid - off] : 0;
        __syncthreads();
        sm[tid] += t;
        __syncthreads();
    }
    if (tid < nb) g_bsum[tid] = sm[tid];
}

__global__ void k_scan3(int N) {  // finalize offsets + cursors (same 1024 blocking)
    int i = blockIdx.x * 1024 + threadIdx.x;
    if (i >= N) return;
    int pre = (blockIdx.x > 0) ? g_bsum[blockIdx.x - 1] : 0;
    int inc = g_scan[i] + pre;
    g_off[i + 1] = inc;
    g_cur[i] = inc - g_cnt[i];
    if (i == 0) g_off[0] = 0;
}

__global__ void k_scatter(const void* __restrict__ ei, int E, int N) {
    int t = blockIdx.x * blockDim.x + threadIdx.x;
    int src, dst;
    if (t < E) {
        src = edge_at(ei, t);
        dst = edge_at(ei, E + t);
        if ((unsigned)src >= (unsigned)N || (unsigned)dst >= (unsigned)N) return;
    }
    else if (t < E + N) { src = dst = t - E; }
    else return;
    int pos = atomicAdd(&g_cur[dst], 1);
    g_csrc[pos] = src;
}

// ---------------- SGEMM (BM=128, BN=128, BK=8, 256 thr, 8x8 micro-tile) ----
// A selected at compile time: ASEL 0 = external ptr, 1 = g_x1, 2 = g_agg
// MODE 0: C = A@B into g_h (B is [K,128] row-major)
// MODE 1: layer-3: B row j is W3[(j%128), (j/128)*128 + :], epilogue
//         Cext = 0.25*acc + bias[col] + g_x2[row,col]
template <int KDIM, int MODE, int ASEL>
__global__ void k_sgemm(const float* __restrict__ Aext, const float* __restrict__ B,
                        float* __restrict__ Cext, const float* __restrict__ bias,
                        int M)
{
    const float* A = (ASEL == 0) ? Aext : (ASEL == 1) ? (const float*)g_x1
                                                      : (const float*)g_agg;
    float* C = (MODE == 1) ? Cext : (float*)g_h;

    __shared__ float As[8][128];
    __shared__ float Bs[8][128];
    const int tid = threadIdx.x;
    const int tx = tid & 15, ty = tid >> 4;
    const int rowBase = blockIdx.x * 128;

    float acc[8][8];
    #pragma unroll
    for (int i = 0; i < 8; i++)
        #pragma unroll
        for (int j = 0; j < 8; j++) acc[i][j] = 0.f;

    const int aRow = tid >> 1;
    const int aCol = (tid & 1) * 4;
    const int bRow = tid >> 5;
    const int bCol = (tid & 31) * 4;

    for (int k0 = 0; k0 < KDIM; k0 += 8) {
        float4 av = make_float4(0.f, 0.f, 0.f, 0.f);
        int gr = rowBase + aRow;
        if (gr < M) av = *(const float4*)&A[(size_t)gr * KDIM + k0 + aCol];
        As[aCol + 0][aRow] = av.x; As[aCol + 1][aRow] = av.y;
        As[aCol + 2][aRow] = av.z; As[aCol + 3][aRow] = av.w;

        int j = k0 + bRow;
        const float* brow;
        if (MODE == 1) brow = B + (size_t)(j & 127) * 512 + (size_t)(j >> 7) * 128;
        else           brow = B + (size_t)j * 128;
        *(float4*)&Bs[bRow][bCol] = *(const float4*)&brow[bCol];
        __syncthreads();

        #pragma unroll
        for (int kk = 0; kk < 8; kk++) {
            float ra[8], rb[8];
            #pragma unroll
            for (int i = 0; i < 8; i++) ra[i] = As[kk][ty * 8 + i];
            #pragma unroll
            for (int j2 = 0; j2 < 8; j2++) rb[j2] = Bs[kk][tx * 8 + j2];
            #pragma unroll
            for (int i = 0; i < 8; i++)
                #pragma unroll
                for (int j2 = 0; j2 < 8; j2++) acc[i][j2] += ra[i] * rb[j2];
        }
        __syncthreads();
    }

    #pragma unroll
    for (int i = 0; i < 8; i++) {
        int r = rowBase + ty * 8 + i;
        if (r >= M) continue;
        #pragma unroll
        for (int j2 = 0; j2 < 8; j2++) {
            int c = tx * 8 + j2;
            float v = acc[i][j2];
            if (MODE == 1) v = 0.25f * v + bias[c] + g_x2[(size_t)r * 128 + c];
            C[(size_t)r * 128 + c] = v;
        }
    }
}

// ---------------- attention scores (layers 1/2): s = <h[n,h,:], a[h,:]> -----
__global__ void k_scores(const float* __restrict__ asrc,
                         const float* __restrict__ adst, int N)
{
    int warp = (blockIdx.x * blockDim.x + threadIdx.x) >> 5;
    if (warp >= N) return;
    int lane = threadIdx.x & 31;
    const float* hr = g_h + (size_t)warp * 128;
    float ps[4], pd[4];
    #pragma unroll
    for (int hh = 0; hh < 4; hh++) {
        float v = hr[hh * 32 + lane];
        ps[hh] = v * asrc[hh * 32 + lane];
        pd[hh] = v * adst[hh * 32 + lane];
    }
    #pragma unroll
    for (int o = 16; o > 0; o >>= 1)
        #pragma unroll
        for (int hh = 0; hh < 4; hh++) {
            ps[hh] += __shfl_xor_sync(0xffffffffu, ps[hh], o);
            pd[hh] += __shfl_xor_sync(0xffffffffu, pd[hh], o);
        }
    if (lane == 0) {
        #pragma unroll
        for (int hh = 0; hh < 4; hh++) {
            g_ss[warp * 4 + hh] = ps[hh];
            g_sd[warp * 4 + hh] = pd[hh];
        }
    }
}

// ---------------- per-node softmax + aggregate (layers 1/2) -----------------
// warp per node: phase1 edge-parallel max, phase2 feature-parallel accumulate
// LAYER 1: xin = external x, xout = g_x1.  LAYER 2: xin = g_x1, xout = g_x2.
template <int LAYER>
__global__ void k_agg(const float* __restrict__ xext,
                      const float* __restrict__ bias, int N)
{
    const float* xin = (LAYER == 1) ? xext : (const float*)g_x1;
    float* xout = (LAYER == 1) ? (float*)g_x1 : (float*)g_x2;

    int warp = (blockIdx.x * blockDim.x + threadIdx.x) >> 5;
    if (warp >= N) return;
    int lane = threadIdx.x & 31;
    int beg = g_off[warp], end = g_off[warp + 1];

    float4 sdv = *(const float4*)(g_sd + 4 * warp);
    float m[4] = {-1e30f, -1e30f, -1e30f, -1e30f};
    for (int i = beg + lane; i < end; i += 32) {
        int s = g_csrc[i];
        float4 sv = *(const float4*)(g_ss + 4 * s);
        m[0] = fmaxf(m[0], lrelu(sv.x + sdv.x));
        m[1] = fmaxf(m[1], lrelu(sv.y + sdv.y));
        m[2] = fmaxf(m[2], lrelu(sv.z + sdv.z));
        m[3] = fmaxf(m[3], lrelu(sv.w + sdv.w));
    }
    #pragma unroll
    for (int o = 16; o > 0; o >>= 1)
        #pragma unroll
        for (int hh = 0; hh < 4; hh++)
            m[hh] = fmaxf(m[hh], __shfl_xor_sync(0xffffffffu, m[hh], o));

    float acc[4] = {0.f, 0.f, 0.f, 0.f};
    float z[4]   = {0.f, 0.f, 0.f, 0.f};
    for (int i = beg; i < end; i++) {
        int s = g_csrc[i];
        float4 sv = *(const float4*)(g_ss + 4 * s);
        const float* hr = g_h + (size_t)s * 128;
        float e0 = lrelu(sv.x + sdv.x), e1 = lrelu(sv.y + sdv.y);
        float e2 = lrelu(sv.z + sdv.z), e3 = lrelu(sv.w + sdv.w);
        float p0 = __expf(e0 - m[0]), p1 = __expf(e1 - m[1]);
        float p2 = __expf(e2 - m[2]), p3 = __expf(e3 - m[3]);
        z[0] += p0; z[1] += p1; z[2] += p2; z[3] += p3;
        acc[0] += p0 * hr[lane];
        acc[1] += p1 * hr[32 + lane];
        acc[2] += p2 * hr[64 + lane];
        acc[3] += p3 * hr[96 + lane];
    }
    #pragma unroll
    for (int hh = 0; hh < 4; hh++) {
        int f = hh * 32 + lane;
        float v = acc[hh] / (z[hh] + 1e-16f) + bias[f] + xin[(size_t)warp * 128 + f];
        v = v > 0.f ? v : expm1f(v);   // ELU
        xout[(size_t)warp * 128 + f] = v;
    }
}

// ---------------- layer-3 small weights: ws[k,h] = sum_f W3[k,h*128+f]*a[h,f]
__global__ void k_wsmall(const float* __restrict__ W3, const float* __restrict__ as3,
                         const float* __restrict__ ad3)
{
    int t = blockIdx.x * blockDim.x + threadIdx.x;
    if (t >= 1024) return;
    int which = t >> 9;
    int idx = t & 511;
    int k = idx >> 2, hh = idx & 3;
    const float* a = which ? ad3 : as3;
    const float* wrow = W3 + (size_t)k * 512 + hh * 128;
    float s = 0.f;
    for (int f = 0; f < 128; f++) s += wrow[f] * a[hh * 128 + f];
    if (which) g_wd[k * 4 + hh] = s; else g_ws[k * 4 + hh] = s;
}

// ---------------- layer-3 scores: s = x2 @ ws / wd ----------------
__global__ void k_scores3(int N)
{
    int warp = (blockIdx.x * blockDim.x + threadIdx.x) >> 5;
    if (warp >= N) return;
    int lane = threadIdx.x & 31;
    const float* xr = g_x2 + (size_t)warp * 128;
    float ps[4] = {0.f, 0.f, 0.f, 0.f}, pd[4] = {0.f, 0.f, 0.f, 0.f};
    #pragma unroll
    for (int kk = 0; kk < 4; kk++) {
        int k = kk * 32 + lane;
        float xv = xr[k];
        #pragma unroll
        for (int hh = 0; hh < 4; hh++) {
            ps[hh] += xv * g_ws[k * 4 + hh];
            pd[hh] += xv * g_wd[k * 4 + hh];
        }
    }
    #pragma unroll
    for (int o = 16; o > 0; o >>= 1)
        #pragma unroll
        for (int hh = 0; hh < 4; hh++) {
            ps[hh] += __shfl_xor_sync(0xffffffffu, ps[hh], o);
            pd[hh] += __shfl_xor_sync(0xffffffffu, pd[hh], o);
        }
    if (lane == 0) {
        #pragma unroll
        for (int hh = 0; hh < 4; hh++) {
            g_ss[warp * 4 + hh] = ps[hh];
            g_sd[warp * 4 + hh] = pd[hh];
        }
    }
}

// ---------------- layer-3 aggregate: agg[n,h*128+k] = sum_e alpha_h x2[src,k]
__global__ void k_agg3(int N)
{
    int warp = (blockIdx.x * blockDim.x + threadIdx.x) >> 5;
    if (warp >= N) return;
    int lane = threadIdx.x & 31;
    int beg = g_off[warp], end = g_off[warp + 1];

    float4 sdv = *(const float4*)(g_sd + 4 * warp);
    float m[4] = {-1e30f, -1e30f, -1e30f, -1e30f};
    for (int i = beg + lane; i < end; i += 32) {
        int s = g_csrc[i];
        float4 sv = *(const float4*)(g_ss + 4 * s);
        m[0] = fmaxf(m[0], lrelu(sv.x + sdv.x));
        m[1] = fmaxf(m[1], lrelu(sv.y + sdv.y));
        m[2] = fmaxf(m[2], lrelu(sv.z + sdv.z));
        m[3] = fmaxf(m[3], lrelu(sv.w + sdv.w));
    }
    #pragma unroll
    for (int o = 16; o > 0; o >>= 1)
        #pragma unroll
        for (int hh = 0; hh < 4; hh++)
            m[hh] = fmaxf(m[hh], __shfl_xor_sync(0xffffffffu, m[hh], o));

    float acc[4][4];
    #pragma unroll
    for (int hh = 0; hh < 4; hh++)
        #pragma unroll
        for (int kk = 0; kk < 4; kk++) acc[hh][kk] = 0.f;
    float z[4] = {0.f, 0.f, 0.f, 0.f};

    for (int i = beg; i < end; i++) {
        int s = g_csrc[i];
        float4 sv = *(const float4*)(g_ss + 4 * s);
        const float* xr = g_x2 + (size_t)s * 128;
        float xv[4];
        #pragma unroll
        for (int kk = 0; kk < 4; kk++) xv[kk] = xr[kk * 32 + lane];
        float e[4] = {lrelu(sv.x + sdv.x), lrelu(sv.y + sdv.y),
                      lrelu(sv.z + sdv.z), lrelu(sv.w + sdv.w)};
        #pragma unroll
        for (int hh = 0; hh < 4; hh++) {
            float p = __expf(e[hh] - m[hh]);
            z[hh] += p;
            #pragma unroll
            for (int kk = 0; kk < 4; kk++) acc[hh][kk] += p * xv[kk];
        }
    }
    #pragma unroll
    for (int hh = 0; hh < 4; hh++) {
        float inv = 1.f / (z[hh] + 1e-16f);
        #pragma unroll
        for (int kk = 0; kk < 4; kk++)
            g_agg[(size_t)warp * 512 + hh * 128 + kk * 32 + lane] = acc[hh][kk] * inv;
    }
}

// ---------------- host entry ----------------
extern "C" void kernel_launch(void* const* d_in, const int* in_sizes, int n_in,
                              void* d_out, int out_size)
{
    const float* x   = (const float*)d_in[0];
    const void*  ei  = d_in[1];
    const float* W1  = (const float*)d_in[2];
    const float* as1 = (const float*)d_in[3];
    const float* ad1 = (const float*)d_in[4];
    const float* b1  = (const float*)d_in[5];
    const float* W2  = (const float*)d_in[6];
    const float* as2 = (const float*)d_in[7];
    const float* ad2 = (const float*)d_in[8];
    const float* b2  = (const float*)d_in[9];
    const float* W3  = (const float*)d_in[10];
    const float* as3 = (const float*)d_in[11];
    const float* ad3 = (const float*)d_in[12];
    const float* b3  = (const float*)d_in[13];

    int N = in_sizes[0] / 128;
    int E = in_sizes[1] / 2;

    int nb = (N + 1023) / 1024;
    int nsamp = (2 * E < 8192) ? 2 * E : 8192;

    // edge dtype detect + CSR build
    k_detect<<<1, 512>>>((const int*)ei, nsamp);
    k_init_cnt<<<nb, 1024>>>(N);
    k_hist<<<(E + 255) / 256, 256>>>(ei, E, N);
    k_scan1<<<nb, 1024>>>(N);
    k_scan2<<<1, 1024>>>(nb);
    k_scan3<<<nb, 1024>>>(N);
    k_scatter<<<(E + N + 255) / 256, 256>>>(ei, E, N);

    int gemmBlocks = (N + 127) / 128;
    int aggBlocks  = (N + 7) / 8;   // 8 warps (nodes) per 256-thread block

    // layer 1
    k_sgemm<128, 0, 0><<<gemmBlocks, 256>>>(x, W1, nullptr, nullptr, N);
    k_scores<<<aggBlocks, 256>>>(as1, ad1, N);
    k_agg<1><<<aggBlocks, 256>>>(x, b1, N);

    // layer 2
    k_sgemm<128, 0, 1><<<gemmBlocks, 256>>>(nullptr, W2, nullptr, nullptr, N);
    k_scores<<<aggBlocks, 256>>>(as2, ad2, N);
    k_agg<2><<<aggBlocks, 256>>>(nullptr, b2, N);

    // layer 3 (never materializes h3 = [N,4,128])
    k_wsmall<<<4, 256>>>(W3, as3, ad3);
    k_scores3<<<aggBlocks, 256>>>(N);
    k_agg3<<<aggBlocks, 256>>>(N);
    k_sgemm<512, 1, 2><<<gemmBlocks, 256>>>(nullptr, W3, (float*)d_out, b3, N);
}

// round 5
// speedup vs baseline: 1.6009x; 1.6009x over previous
#include <cuda_runtime.h>
#include <math.h>

// Problem caps (N=100000, E=800000 per setup_inputs; small safety margin)
#define NCAP 100352
#define ECAP 802816
#define ETCAP (ECAP + NCAP)

// Retry of round-3 TF32 tensor-core kernel: round-4 failure was a harness-side
// "device busy" before any kernel ran; the kernel itself was never executed.

// ---------------- device scratch (static, no allocation) ----------------
__device__ float g_h  [(size_t)NCAP * 128];   // per-layer transformed features
__device__ float g_x1 [(size_t)NCAP * 128];   // layer-1 output
__device__ float g_x2 [(size_t)NCAP * 128];   // layer-2 output
__device__ float g_agg[(size_t)NCAP * 512];   // layer-3 weighted x2 aggregate
__device__ float g_ss [NCAP * 4];             // s_src per node/head
__device__ float g_sd [NCAP * 4];             // s_dst per node/head
__device__ int   g_cnt [NCAP];
__device__ int   g_scan[NCAP];
__device__ int   g_bsum[1024];
__device__ int   g_off [NCAP + 1];
__device__ int   g_cur [NCAP];
__device__ int   g_csrc[ETCAP];
__device__ float g_ws[128 * 4];               // W3_h @ a_src3_h
__device__ float g_wd[128 * 4];               // W3_h @ a_dst3_h
__device__ int   g_i64;                       // 1 if edge_index is int64, 0 if int32

__device__ __forceinline__ float lrelu(float e) { return e > 0.f ? e : 0.2f * e; }

__device__ __forceinline__ int edge_at(const void* ei, int idx) {
    if (g_i64) return (int)((const long long*)ei)[idx];
    return ((const int*)ei)[idx];
}

// ---------------- edge dtype detection ----------------
__global__ void k_detect(const int* __restrict__ ei32, int nsamp) {
    __shared__ int any;
    if (threadIdx.x == 0) any = 0;
    __syncthreads();
    for (int i = threadIdx.x * 2 + 1; i < nsamp; i += 512)
        if (ei32[i] != 0) { any = 1; break; }
    __syncthreads();
    if (threadIdx.x == 0) g_i64 = any ? 0 : 1;
}

// ---------------- CSR build ----------------
__global__ void k_init_cnt(int N) {
    int i = blockIdx.x * blockDim.x + threadIdx.x;
    if (i < N) g_cnt[i] = 1;   // self loop
}

__global__ void k_hist(const void* __restrict__ ei, int E, int N) {
    int e = blockIdx.x * blockDim.x + threadIdx.x;
    if (e >= E) return;
    int dst = edge_at(ei, E + e);
    if ((unsigned)dst < (unsigned)N) atomicAdd(&g_cnt[dst], 1);
}

__global__ void k_scan1(int N) {
    __shared__ int sm[1024];
    int tid = threadIdx.x;
    int i = blockIdx.x * 1024 + tid;
    sm[tid] = (i < N) ? g_cnt[i] : 0;
    __syncthreads();
    for (int off = 1; off < 1024; off <<= 1) {
        int t = (tid >= off) ? sm[tid - off] : 0;
        __syncthreads();
        sm[tid] += t;
        __syncthreads();
    }
    if (i < N) g_scan[i] = sm[tid];
    if (tid == 1023) g_bsum[blockIdx.x] = sm[1023];
}

__global__ void k_scan2(int nb) {
    __shared__ int sm[1024];
    int tid = threadIdx.x;
    sm[tid] = (tid < nb) ? g_bsum[tid] : 0;
    __syncthreads();
    for (int off = 1; off < 1024; off <<= 1) {
        int t = (tid >= off) ? sm[tid - off] : 0;
        __syncthreads();
        sm[tid] += t;
        __syncthreads();
    }
    if (tid < nb) g_bsum[tid] = sm[tid];
}

__global__ void k_scan3(int N) {
    int i = blockIdx.x * 1024 + threadIdx.x;
    if (i >= N) return;
    int pre = (blockIdx.x > 0) ? g_bsum[blockIdx.x - 1] : 0;
    int inc = g_scan[i] + pre;
    g_off[i + 1] = inc;
    g_cur[i] = inc - g_cnt[i];
    if (i == 0) g_off[0] = 0;
}

__global__ void k_scatter(const void* __restrict__ ei, int E, int N) {
    int t = blockIdx.x * blockDim.x + threadIdx.x;
    int src, dst;
    if (t < E) {
        src = edge_at(ei, t);
        dst = edge_at(ei, E + t);
        if ((unsigned)src >= (unsigned)N || (unsigned)dst >= (unsigned)N) return;
    }
    else if (t < E + N) { src = dst = t - E; }
    else return;
    int pos = atomicAdd(&g_cur[dst], 1);
    g_csrc[pos] = src;
}

// ---------------- TF32 tensor-core GEMM ----------------
// BM=128, BN=128 (all GEMMs have N=128), BK=16, 256 threads, 8 warps.
// Warp tile 32x64 via m16n8k8 mma (2 m-tiles x 8 n-tiles).
// ASEL: 0 = external A, 1 = g_x1, 2 = g_agg.
// MODE 0: C = A@B into g_h.   MODE 1: Cext = 0.25*acc + bias + g_x2 (layer 3).

__device__ __forceinline__ unsigned f2tf(float f) {
    unsigned u;
    asm("cvt.rna.tf32.f32 %0, %1;" : "=r"(u) : "f"(f));
    return u;
}
__device__ __forceinline__ uint4 cvt4(float4 v) {
    uint4 u;
    u.x = f2tf(v.x); u.y = f2tf(v.y); u.z = f2tf(v.z); u.w = f2tf(v.w);
    return u;
}
__device__ __forceinline__ void mma_tf32(float* d, const unsigned* a, const unsigned* b) {
    asm volatile(
        "mma.sync.aligned.m16n8k8.row.col.f32.tf32.tf32.f32 "
        "{%0,%1,%2,%3}, {%4,%5,%6,%7}, {%8,%9}, {%0,%1,%2,%3};\n"
        : "+f"(d[0]), "+f"(d[1]), "+f"(d[2]), "+f"(d[3])
        : "r"(a[0]), "r"(a[1]), "r"(a[2]), "r"(a[3]), "r"(b[0]), "r"(b[1]));
}

#define AS_STRIDE 20
#define BS_STRIDE 136

template <int KDIM, int MODE, int ASEL>
__global__ void __launch_bounds__(256, 2)
k_mma(const float* __restrict__ Aext, const float* __restrict__ B,
      float* __restrict__ Cext, const float* __restrict__ bias, int M)
{
    const float* A = (ASEL == 0) ? Aext : (ASEL == 1) ? (const float*)g_x1
                                                      : (const float*)g_agg;
    __shared__ unsigned As[128 * AS_STRIDE];
    __shared__ unsigned Bs[16 * BS_STRIDE];

    const int tid = threadIdx.x;
    const int lane = tid & 31;
    const int wid = tid >> 5;
    const int warpM = wid >> 1, warpN = wid & 1;
    const int rowBase = blockIdx.x * 128;

    // global tile load mapping
    const int aRow = tid >> 2;            // 0..63 (+64 for second half)
    const int aCol = (tid & 3) * 4;       // 0,4,8,12
    const int bRow = tid >> 4;            // 0..15
    const int bCol = (tid & 15) * 4;      // 0..60 (+64 for second half)

    float acc[2][8][4];
    #pragma unroll
    for (int t = 0; t < 2; t++)
        #pragma unroll
        for (int j = 0; j < 8; j++)
            #pragma unroll
            for (int q = 0; q < 4; q++) acc[t][j][q] = 0.f;

    const float4 z4 = make_float4(0.f, 0.f, 0.f, 0.f);
    float4 pa0, pa1, pb0, pb1;

    // prefetch k0 = 0
    {
        int r0 = rowBase + aRow;
        pa0 = (r0 < M) ? *(const float4*)&A[(size_t)r0 * KDIM + aCol] : z4;
        int r1 = r0 + 64;
        pa1 = (r1 < M) ? *(const float4*)&A[(size_t)r1 * KDIM + aCol] : z4;
        int j = bRow;
        const float* br = (MODE == 1) ? B + (size_t)(j & 127) * 512 + (size_t)(j >> 7) * 128
                                      : B + (size_t)j * 128;
        pb0 = *(const float4*)&br[bCol];
        pb1 = *(const float4*)&br[bCol + 64];
    }

    for (int k0 = 0; k0 < KDIM; k0 += 16) {
        // store current tile (with tf32 round-to-nearest)
        *(uint4*)&As[aRow * AS_STRIDE + aCol]        = cvt4(pa0);
        *(uint4*)&As[(aRow + 64) * AS_STRIDE + aCol] = cvt4(pa1);
        *(uint4*)&Bs[bRow * BS_STRIDE + bCol]        = cvt4(pb0);
        *(uint4*)&Bs[bRow * BS_STRIDE + bCol + 64]   = cvt4(pb1);
        __syncthreads();

        // prefetch next tile (overlaps with mma compute)
        if (k0 + 16 < KDIM) {
            int kn = k0 + 16;
            int r0 = rowBase + aRow;
            pa0 = (r0 < M) ? *(const float4*)&A[(size_t)r0 * KDIM + kn + aCol] : z4;
            int r1 = r0 + 64;
            pa1 = (r1 < M) ? *(const float4*)&A[(size_t)r1 * KDIM + kn + aCol] : z4;
            int j = kn + bRow;
            const float* br = (MODE == 1) ? B + (size_t)(j & 127) * 512 + (size_t)(j >> 7) * 128
                                          : B + (size_t)j * 128;
            pb0 = *(const float4*)&br[bCol];
            pb1 = *(const float4*)&br[bCol + 64];
        }

        #pragma unroll
        for (int s = 0; s < 2; s++) {
            const int kc = s * 8;
            unsigned af[2][4], bf[8][2];
            const int arow = warpM * 32 + (lane >> 2);
            const int acol = kc + (lane & 3);
            #pragma unroll
            for (int t = 0; t < 2; t++) {
                int r = arow + t * 16;
                af[t][0] = As[r * AS_STRIDE + acol];
                af[t][1] = As[(r + 8) * AS_STRIDE + acol];
                af[t][2] = As[r * AS_STRIDE + acol + 4];
                af[t][3] = As[(r + 8) * AS_STRIDE + acol + 4];
            }
            const int bk = kc + (lane & 3);
            #pragma unroll
            for (int j = 0; j < 8; j++) {
                int bn = warpN * 64 + j * 8 + (lane >> 2);
                bf[j][0] = Bs[bk * BS_STRIDE + bn];
                bf[j][1] = Bs[(bk + 4) * BS_STRIDE + bn];
            }
            #pragma unroll
            for (int t = 0; t < 2; t++)
                #pragma unroll
                for (int j = 0; j < 8; j++)
                    mma_tf32(acc[t][j], af[t], bf[j]);
        }
        __syncthreads();
    }

    // epilogue
    #pragma unroll
    for (int t = 0; t < 2; t++) {
        int r0 = rowBase + warpM * 32 + t * 16 + (lane >> 2);
        int r1 = r0 + 8;
        #pragma unroll
        for (int j = 0; j < 8; j++) {
            int c = warpN * 64 + j * 8 + 2 * (lane & 3);
            if (MODE == 0) {
                // rows < NCAP always; g_h is padded, unguarded store is safe
                *(float2*)&g_h[(size_t)r0 * 128 + c] = make_float2(acc[t][j][0], acc[t][j][1]);
                *(float2*)&g_h[(size_t)r1 * 128 + c] = make_float2(acc[t][j][2], acc[t][j][3]);
            } else {
                if (r0 < M) {
                    float v0 = 0.25f * acc[t][j][0] + bias[c]     + g_x2[(size_t)r0 * 128 + c];
                    float v1 = 0.25f * acc[t][j][1] + bias[c + 1] + g_x2[(size_t)r0 * 128 + c + 1];
                    *(float2*)&Cext[(size_t)r0 * 128 + c] = make_float2(v0, v1);
                }
                if (r1 < M) {
                    float v2 = 0.25f * acc[t][j][2] + bias[c]     + g_x2[(size_t)r1 * 128 + c];
                    float v3 = 0.25f * acc[t][j][3] + bias[c + 1] + g_x2[(size_t)r1 * 128 + c + 1];
                    *(float2*)&Cext[(size_t)r1 * 128 + c] = make_float2(v2, v3);
                }
            }
        }
    }
}

// ---------------- attention scores (layers 1/2): s = <h[n,h,:], a[h,:]> -----
__global__ void k_scores(const float* __restrict__ asrc,
                         const float* __restrict__ adst, int N)
{
    int warp = (blockIdx.x * blockDim.x + threadIdx.x) >> 5;
    if (warp >= N) return;
    int lane = threadIdx.x & 31;
    const float* hr = g_h + (size_t)warp * 128;
    float ps[4], pd[4];
    #pragma unroll
    for (int hh = 0; hh < 4; hh++) {
        float v = hr[hh * 32 + lane];
        ps[hh] = v * asrc[hh * 32 + lane];
        pd[hh] = v * adst[hh * 32 + lane];
    }
    #pragma unroll
    for (int o = 16; o > 0; o >>= 1)
        #pragma unroll
        for (int hh = 0; hh < 4; hh++) {
            ps[hh] += __shfl_xor_sync(0xffffffffu, ps[hh], o);
            pd[hh] += __shfl_xor_sync(0xffffffffu, pd[hh], o);
        }
    if (lane == 0) {
        #pragma unroll
        for (int hh = 0; hh < 4; hh++) {
            g_ss[warp * 4 + hh] = ps[hh];
            g_sd[warp * 4 + hh] = pd[hh];
        }
    }
}

// ---------------- per-node softmax + aggregate (layers 1/2) -----------------
template <int LAYER>
__global__ void k_agg(const float* __restrict__ xext,
                      const float* __restrict__ bias, int N)
{
    const float* xin = (LAYER == 1) ? xext : (const float*)g_x1;
    float* xout = (LAYER == 1) ? (float*)g_x1 : (float*)g_x2;

    int warp = (blockIdx.x * blockDim.x + threadIdx.x) >> 5;
    if (warp >= N) return;
    int lane = threadIdx.x & 31;
    int beg = g_off[warp], end = g_off[warp + 1];

    float4 sdv = *(const float4*)(g_sd + 4 * warp);
    float m[4] = {-1e30f, -1e30f, -1e30f, -1e30f};
    for (int i = beg + lane; i < end; i += 32) {
        int s = g_csrc[i];
        float4 sv = *(const float4*)(g_ss + 4 * s);
        m[0] = fmaxf(m[0], lrelu(sv.x + sdv.x));
        m[1] = fmaxf(m[1], lrelu(sv.y + sdv.y));
        m[2] = fmaxf(m[2], lrelu(sv.z + sdv.z));
        m[3] = fmaxf(m[3], lrelu(sv.w + sdv.w));
    }
    #pragma unroll
    for (int o = 16; o > 0; o >>= 1)
        #pragma unroll
        for (int hh = 0; hh < 4; hh++)
            m[hh] = fmaxf(m[hh], __shfl_xor_sync(0xffffffffu, m[hh], o));

    float acc[4] = {0.f, 0.f, 0.f, 0.f};
    float z[4]   = {0.f, 0.f, 0.f, 0.f};
    for (int i = beg; i < end; i++) {
        int s = g_csrc[i];
        float4 sv = *(const float4*)(g_ss + 4 * s);
        const float* hr = g_h + (size_t)s * 128;
        float e0 = lrelu(sv.x + sdv.x), e1 = lrelu(sv.y + sdv.y);
        float e2 = lrelu(sv.z + sdv.z), e3 = lrelu(sv.w + sdv.w);
        float p0 = __expf(e0 - m[0]), p1 = __expf(e1 - m[1]);
        float p2 = __expf(e2 - m[2]), p3 = __expf(e3 - m[3]);
        z[0] += p0; z[1] += p1; z[2] += p2; z[3] += p3;
        acc[0] += p0 * hr[lane];
        acc[1] += p1 * hr[32 + lane];
        acc[2] += p2 * hr[64 + lane];
        acc[3] += p3 * hr[96 + lane];
    }
    #pragma unroll
    for (int hh = 0; hh < 4; hh++) {
        int f = hh * 32 + lane;
        float v = acc[hh] / (z[hh] + 1e-16f) + bias[f] + xin[(size_t)warp * 128 + f];
        v = v > 0.f ? v : expm1f(v);   // ELU
        xout[(size_t)warp * 128 + f] = v;
    }
}

// ---------------- layer-3 small weights: ws[k,h] = sum_f W3[k,h*128+f]*a[h,f]
__global__ void k_wsmall(const float* __restrict__ W3, const float* __restrict__ as3,
                         const float* __restrict__ ad3)
{
    int t = blockIdx.x * blockDim.x + threadIdx.x;
    if (t >= 1024) return;
    int which = t >> 9;
    int idx = t & 511;
    int k = idx >> 2, hh = idx & 3;
    const float* a = which ? ad3 : as3;
    const float* wrow = W3 + (size_t)k * 512 + hh * 128;
    float s = 0.f;
    for (int f = 0; f < 128; f++) s += wrow[f] * a[hh * 128 + f];
    if (which) g_wd[k * 4 + hh] = s; else g_ws[k * 4 + hh] = s;
}

// ---------------- layer-3 scores: s = x2 @ ws / wd ----------------
__global__ void k_scores3(int N)
{
    int warp = (blockIdx.x * blockDim.x + threadIdx.x) >> 5;
    if (warp >= N) return;
    int lane = threadIdx.x & 31;
    const float* xr = g_x2 + (size_t)warp * 128;
    float ps[4] = {0.f, 0.f, 0.f, 0.f}, pd[4] = {0.f, 0.f, 0.f, 0.f};
    #pragma unroll
    for (int kk = 0; kk < 4; kk++) {
        int k = kk * 32 + lane;
        float xv = xr[k];
        #pragma unroll
        for (int hh = 0; hh < 4; hh++) {
            ps[hh] += xv * g_ws[k * 4 + hh];
            pd[hh] += xv * g_wd[k * 4 + hh];
        }
    }
    #pragma unroll
    for (int o = 16; o > 0; o >>= 1)
        #pragma unroll
        for (int hh = 0; hh < 4; hh++) {
            ps[hh] += __shfl_xor_sync(0xffffffffu, ps[hh], o);
            pd[hh] += __shfl_xor_sync(0xffffffffu, pd[hh], o);
        }
    if (lane == 0) {
        #pragma unroll
        for (int hh = 0; hh < 4; hh++) {
            g_ss[warp * 4 + hh] = ps[hh];
            g_sd[warp * 4 + hh] = pd[hh];
        }
    }
}

// ---------------- layer-3 aggregate: agg[n,h*128+k] = sum_e alpha_h x2[src,k]
__global__ void k_agg3(int N)
{
    int warp = (blockIdx.x * blockDim.x + threadIdx.x) >> 5;
    if (warp >= N) return;
    int lane = threadIdx.x & 31;
    int beg = g_off[warp], end = g_off[warp + 1];

    float4 sdv = *(const float4*)(g_sd + 4 * warp);
    float m[4] = {-1e30f, -1e30f, -1e30f, -1e30f};
    for (int i = beg + lane; i < end; i += 32) {
        int s = g_csrc[i];
        float4 sv = *(const float4*)(g_ss + 4 * s);
        m[0] = fmaxf(m[0], lrelu(sv.x + sdv.x));
        m[1] = fmaxf(m[1], lrelu(sv.y + sdv.y));
        m[2] = fmaxf(m[2], lrelu(sv.z + sdv.z));
        m[3] = fmaxf(m[3], lrelu(sv.w + sdv.w));
    }
    #pragma unroll
    for (int o = 16; o > 0; o >>= 1)
        #pragma unroll
        for (int hh = 0; hh < 4; hh++)
            m[hh] = fmaxf(m[hh], __shfl_xor_sync(0xffffffffu, m[hh], o));

    float acc[4][4];
    #pragma unroll
    for (int hh = 0; hh < 4; hh++)
        #pragma unroll
        for (int kk = 0; kk < 4; kk++) acc[hh][kk] = 0.f;
    float z[4] = {0.f, 0.f, 0.f, 0.f};

    for (int i = beg; i < end; i++) {
        int s = g_csrc[i];
        float4 sv = *(const float4*)(g_ss + 4 * s);
        const float* xr = g_x2 + (size_t)s * 128;
        float xv[4];
        #pragma unroll
        for (int kk = 0; kk < 4; kk++) xv[kk] = xr[kk * 32 + lane];
        float e[4] = {lrelu(sv.x + sdv.x), lrelu(sv.y + sdv.y),
                      lrelu(sv.z + sdv.z), lrelu(sv.w + sdv.w)};
        #pragma unroll
        for (int hh = 0; hh < 4; hh++) {
            float p = __expf(e[hh] - m[hh]);
            z[hh] += p;
            #pragma unroll
            for (int kk = 0; kk < 4; kk++) acc[hh][kk] += p * xv[kk];
        }
    }
    #pragma unroll
    for (int hh = 0; hh < 4; hh++) {
        float inv = 1.f / (z[hh] + 1e-16f);
        #pragma unroll
        for (int kk = 0; kk < 4; kk++)
            g_agg[(size_t)warp * 512 + hh * 128 + kk * 32 + lane] = acc[hh][kk] * inv;
    }
}

// ---------------- host entry ----------------
extern "C" void kernel_launch(void* const* d_in, const int* in_sizes, int n_in,
                              void* d_out, int out_size)
{
    const float* x   = (const float*)d_in[0];
    const void*  ei  = d_in[1];
    const float* W1  = (const float*)d_in[2];
    const float* as1 = (const float*)d_in[3];
    const float* ad1 = (const float*)d_in[4];
    const float* b1  = (const float*)d_in[5];
    const float* W2  = (const float*)d_in[6];
    const float* as2 = (const float*)d_in[7];
    const float* ad2 = (const float*)d_in[8];
    const float* b2  = (const float*)d_in[9];
    const float* W3  = (const float*)d_in[10];
    const float* as3 = (const float*)d_in[11];
    const float* ad3 = (const float*)d_in[12];
    const float* b3  = (const float*)d_in[13];

    int N = in_sizes[0] / 128;
    int E = in_sizes[1] / 2;

    int nb = (N + 1023) / 1024;
    int nsamp = (2 * E < 8192) ? 2 * E : 8192;

    // edge dtype detect + CSR build
    k_detect<<<1, 512>>>((const int*)ei, nsamp);
    k_init_cnt<<<nb, 1024>>>(N);
    k_hist<<<(E + 255) / 256, 256>>>(ei, E, N);
    k_scan1<<<nb, 1024>>>(N);
    k_scan2<<<1, 1024>>>(nb);
    k_scan3<<<nb, 1024>>>(N);
    k_scatter<<<(E + N + 255) / 256, 256>>>(ei, E, N);

    int gemmBlocks = (N + 127) / 128;
    int aggBlocks  = (N + 7) / 8;   // 8 warps (nodes) per 256-thread block

    // layer 1
    k_mma<128, 0, 0><<<gemmBlocks, 256>>>(x, W1, nullptr, nullptr, N);
    k_scores<<<aggBlocks, 256>>>(as1, ad1, N);
    k_agg<1><<<aggBlocks, 256>>>(x, b1, N);

    // layer 2
    k_mma<128, 0, 1><<<gemmBlocks, 256>>>(nullptr, W2, nullptr, nullptr, N);
    k_scores<<<aggBlocks, 256>>>(as2, ad2, N);
    k_agg<2><<<aggBlocks, 256>>>(nullptr, b2, N);

    // layer 3 (never materializes h3 = [N,4,128])
    k_wsmall<<<4, 256>>>(W3, as3, ad3);
    k_scores3<<<aggBlocks, 256>>>(N);
    k_agg3<<<aggBlocks, 256>>>(N);
    k_mma<512, 1, 2><<<gemmBlocks, 256>>>(nullptr, W3, (float*)d_out, b3, N);
}